// round 2
// baseline (speedup 1.0000x reference)
#include <cuda_runtime.h>
#include <cstddef>

#define BATCH 16
#define NN 128
#define DD 128
#define EE 64
#define HH 256
#define ROWS (BATCH*NN)   // 2048
#define EPSLN 1e-5f

#define GRELU 1
#define GMASK 2

// ---------------- scratch (static device buffers, no allocation) ----------------
__device__ float g_x[ROWS*DD];
__device__ float g_np[ROWS*HH];
__device__ float g_s[ROWS*HH];
__device__ float g_agg[ROWS*HH];
__device__ float g_u1[ROWS*HH];
__device__ float g_u[ROWS*DD];
__device__ float g_cnt[ROWS];

// ---------------- prep: x = nodes * mask ----------------
__global__ void prep_x_kernel(const float* __restrict__ nodes,
                              const int* __restrict__ mask,
                              float* __restrict__ x) {
    int row = blockIdx.x;         // 0..2047
    int d = threadIdx.x;          // 0..127
    float mi = mask[row] ? 1.f : 0.f;
    x[row*DD + d] = nodes[row*DD + d] * mi;
}

// cnt[b*N+i] = mask[b,i] * sum_j mask[b,j]
__global__ void prep_cnt_kernel(const int* __restrict__ mask,
                                float* __restrict__ cnt) {
    int b = blockIdx.x;
    int j = threadIdx.x;          // 0..127
    __shared__ float red[NN];
    float m = mask[b*NN + j] ? 1.f : 0.f;
    red[j] = m;
    __syncthreads();
    for (int s2 = 64; s2 > 0; s2 >>= 1) {
        if (j < s2) red[j] += red[j + s2];
        __syncthreads();
    }
    cnt[b*NN + j] = m * red[0];
}

// ---------------- fused edge GEMM + relu + masked j-reduction ----------------
// s[b,i,h] = m_i * sum_j m_j * relu( np[b,i,h] + b1[h] + sum_e edges[b,i,j,e]*We[e,h] )
__global__ __launch_bounds__(256, 2)
void edge_msg_kernel(const float* __restrict__ edges,
                     const float* __restrict__ We,    // (64,256)
                     const float* __restrict__ b1,    // (256)
                     const float* __restrict__ np,    // (ROWS,256)
                     const int* __restrict__ mask,
                     float* __restrict__ s_out) {
    int row = blockIdx.x;              // b*N + i
    int b = row >> 7;
    int t = threadIdx.x;               // h column, 0..255

    __shared__ float se[8 * EE];       // 8 j-rows of 64 edge features
    __shared__ float smj[8];

    float w[EE];
#pragma unroll
    for (int e = 0; e < EE; e++) w[e] = We[e*HH + t];

    float npv = np[(size_t)row*HH + t] + b1[t];
    float acc = 0.f;

    const float* ebase = edges + (size_t)row * NN * EE;
    const int* mrow = mask + b*NN;

    for (int j0 = 0; j0 < NN; j0 += 8) {
        __syncthreads();
        const float* src = ebase + j0*EE;
        se[t]       = src[t];
        se[t + 256] = src[t + 256];
        if (t < 8) smj[t] = mrow[j0 + t] ? 1.f : 0.f;
        __syncthreads();
#pragma unroll
        for (int jj = 0; jj < 8; jj++) {
            float m = smj[jj];
            const float* r = &se[jj*EE];
            float h0 = npv, h1 = 0.f;
#pragma unroll
            for (int e = 0; e < EE; e += 2) {
                h0 = fmaf(r[e],     w[e],     h0);
                h1 = fmaf(r[e + 1], w[e + 1], h1);
            }
            acc = fmaf(m, fmaxf(h0 + h1, 0.f), acc);
        }
    }
    float mi = mask[row] ? 1.f : 0.f;
    s_out[(size_t)row*HH + t] = acc * mi;
}

// ---------------- generic tiled fp32 GEMM ----------------
// C(M,N) = epilogue( [A | A2](M,K) @ W(K,N) )
// A supplies cols [0,K1), A2 (if non-null) supplies cols [K1,K).
// epilogue: +bias[n]*(rowscale? rowscale[m]:1); relu; *mask[m]
__global__ __launch_bounds__(256)
void gemm_k(int M, int N, int K, int K1,
            const float* __restrict__ A, int lda,
            const float* __restrict__ A2, int lda2,
            const float* __restrict__ W, int ldw,
            const float* __restrict__ bias,
            const float* __restrict__ rowscale,
            const int* __restrict__ maskrow,
            float* __restrict__ C, int ldc, int flags) {
    __shared__ float As[64][17];
    __shared__ float Ws[16][64];

    int tid = threadIdx.x;
    int bm = blockIdx.y * 64, bn = blockIdx.x * 64;
    int tx = tid & 15, ty = tid >> 4;

    int arow = tid >> 2;            // 0..63
    int acol4 = (tid & 3) * 4;      // 0,4,8,12
    int wrow = tid >> 4;            // 0..15
    int wcol4 = (tid & 15) * 4;

    float acc[4][4];
#pragma unroll
    for (int i = 0; i < 4; i++)
#pragma unroll
        for (int j = 0; j < 4; j++) acc[i][j] = 0.f;

    for (int k0 = 0; k0 < K; k0 += 16) {
        // A tile
        {
            int gm = bm + arow;
            int gk = k0 + acol4;
            float4 v;
            if (A2 != nullptr && gk >= K1)
                v = *(const float4*)(A2 + (size_t)gm*lda2 + (gk - K1));
            else
                v = *(const float4*)(A + (size_t)gm*lda + gk);
            As[arow][acol4 + 0] = v.x;
            As[arow][acol4 + 1] = v.y;
            As[arow][acol4 + 2] = v.z;
            As[arow][acol4 + 3] = v.w;
        }
        // W tile
        {
            float4 wv = *(const float4*)(W + (size_t)(k0 + wrow)*ldw + bn + wcol4);
            *(float4*)&Ws[wrow][wcol4] = wv;
        }
        __syncthreads();
#pragma unroll
        for (int k = 0; k < 16; k++) {
            float a0 = As[ty*4 + 0][k];
            float a1 = As[ty*4 + 1][k];
            float a2 = As[ty*4 + 2][k];
            float a3 = As[ty*4 + 3][k];
            float4 bv = *(const float4*)&Ws[k][tx*4];
            acc[0][0] = fmaf(a0, bv.x, acc[0][0]);
            acc[0][1] = fmaf(a0, bv.y, acc[0][1]);
            acc[0][2] = fmaf(a0, bv.z, acc[0][2]);
            acc[0][3] = fmaf(a0, bv.w, acc[0][3]);
            acc[1][0] = fmaf(a1, bv.x, acc[1][0]);
            acc[1][1] = fmaf(a1, bv.y, acc[1][1]);
            acc[1][2] = fmaf(a1, bv.z, acc[1][2]);
            acc[1][3] = fmaf(a1, bv.w, acc[1][3]);
            acc[2][0] = fmaf(a2, bv.x, acc[2][0]);
            acc[2][1] = fmaf(a2, bv.y, acc[2][1]);
            acc[2][2] = fmaf(a2, bv.z, acc[2][2]);
            acc[2][3] = fmaf(a2, bv.w, acc[2][3]);
            acc[3][0] = fmaf(a3, bv.x, acc[3][0]);
            acc[3][1] = fmaf(a3, bv.y, acc[3][1]);
            acc[3][2] = fmaf(a3, bv.z, acc[3][2]);
            acc[3][3] = fmaf(a3, bv.w, acc[3][3]);
        }
        __syncthreads();
    }

#pragma unroll
    for (int i = 0; i < 4; i++) {
        int gm = bm + ty*4 + i;
        float rs = 1.f;
        if (rowscale != nullptr) rs = rowscale[gm];
        float mf = 1.f;
        if (flags & GMASK) mf = maskrow[gm] ? 1.f : 0.f;
#pragma unroll
        for (int j = 0; j < 4; j++) {
            int gn = bn + tx*4 + j;
            float v = acc[i][j];
            if (bias != nullptr) v += bias[gn] * rs;
            if (flags & GRELU) v = fmaxf(v, 0.f);
            v *= mf;
            C[(size_t)gm*ldc + gn] = v;
        }
    }
}

// ---------------- fused residual + LayerNorm: x = LN(x + u*mi)*g + b, then *mi ----
__global__ void ln_kernel(const float* __restrict__ u,
                          const int* __restrict__ mask,
                          const float* __restrict__ gw,
                          const float* __restrict__ bw,
                          float* __restrict__ x) {
    int warp = threadIdx.x >> 5;
    int lane = threadIdx.x & 31;
    int row = blockIdx.x * 8 + warp;
    float mi = mask[row] ? 1.f : 0.f;

    float v[4];
#pragma unroll
    for (int q = 0; q < 4; q++) {
        int d = lane + q*32;
        v[q] = x[(size_t)row*DD + d] + u[(size_t)row*DD + d] * mi;
    }
    float s = v[0] + v[1] + v[2] + v[3];
#pragma unroll
    for (int o = 16; o > 0; o >>= 1) s += __shfl_xor_sync(0xffffffffu, s, o);
    float mu = s * (1.f / DD);
    float var = 0.f;
#pragma unroll
    for (int q = 0; q < 4; q++) { float d2 = v[q] - mu; var += d2*d2; }
#pragma unroll
    for (int o = 16; o > 0; o >>= 1) var += __shfl_xor_sync(0xffffffffu, var, o);
    float rstd = rsqrtf(var * (1.f / DD) + EPSLN);
#pragma unroll
    for (int q = 0; q < 4; q++) {
        int d = lane + q*32;
        x[(size_t)row*DD + d] = ((v[q] - mu) * rstd * gw[d] + bw[d]) * mi;
    }
}

// ---------------- host launch ----------------
extern "C" void kernel_launch(void* const* d_in, const int* in_sizes, int n_in,
                              void* d_out, int out_size) {
    const float* nodes  = (const float*)d_in[0];
    const float* edges  = (const float*)d_in[1];
    const int*   mask   = (const int*)d_in[2];
    const float* msg_w1 = (const float*)d_in[3];   // (L,192,256)
    const float* msg_b1 = (const float*)d_in[4];   // (L,256)
    const float* msg_w2 = (const float*)d_in[5];   // (L,256,256)
    const float* msg_b2 = (const float*)d_in[6];   // (L,256)
    const float* upd_w1 = (const float*)d_in[7];   // (L,384,256)
    const float* upd_b1 = (const float*)d_in[8];   // (L,256)
    const float* upd_w2 = (const float*)d_in[9];   // (L,256,128)
    const float* upd_b2 = (const float*)d_in[10];  // (L,128)
    const float* ln_g   = (const float*)d_in[11];  // (L,128)
    const float* ln_b   = (const float*)d_in[12];  // (L,128)
    const float* out_w1 = (const float*)d_in[13];  // (128,256)
    const float* out_b1 = (const float*)d_in[14];  // (256)
    const float* out_w2 = (const float*)d_in[15];  // (256,128)
    const float* out_b2 = (const float*)d_in[16];  // (128)
    float* out = (float*)d_out;

    float *x, *np, *s, *agg, *u1, *u, *cnt;
    cudaGetSymbolAddress((void**)&x,   g_x);
    cudaGetSymbolAddress((void**)&np,  g_np);
    cudaGetSymbolAddress((void**)&s,   g_s);
    cudaGetSymbolAddress((void**)&agg, g_agg);
    cudaGetSymbolAddress((void**)&u1,  g_u1);
    cudaGetSymbolAddress((void**)&u,   g_u);
    cudaGetSymbolAddress((void**)&cnt, g_cnt);

    prep_x_kernel<<<ROWS, DD>>>(nodes, mask, x);
    prep_cnt_kernel<<<BATCH, NN>>>(mask, cnt);

    for (int l = 0; l < 3; l++) {
        const float* w1n = msg_w1 + (size_t)l * 192 * HH;          // node part rows 0..127
        const float* w1e = w1n + (size_t)DD * HH;                  // edge part rows 128..191
        const float* b1  = msg_b1 + (size_t)l * HH;
        const float* w2  = msg_w2 + (size_t)l * HH * HH;
        const float* b2  = msg_b2 + (size_t)l * HH;
        const float* uw1 = upd_w1 + (size_t)l * 384 * HH;
        const float* ub1 = upd_b1 + (size_t)l * HH;
        const float* uw2 = upd_w2 + (size_t)l * HH * DD;
        const float* ub2 = upd_b2 + (size_t)l * DD;
        const float* lg  = ln_g + (size_t)l * DD;
        const float* lb  = ln_b + (size_t)l * DD;

        // np = x @ w1n      (2048,256,K=128)
        gemm_k<<<dim3(HH/64, ROWS/64), 256>>>(ROWS, HH, DD, 0,
            x, DD, nullptr, 0, w1n, HH, nullptr, nullptr, nullptr, np, HH, 0);

        // s = masked relu-reduce of (np + edges@w1e + b1)
        edge_msg_kernel<<<ROWS, 256>>>(edges, w1e, b1, np, mask, s);

        // agg = s @ w2 + cnt*b2   (2048,256,K=256)
        gemm_k<<<dim3(HH/64, ROWS/64), 256>>>(ROWS, HH, HH, 0,
            s, HH, nullptr, 0, w2, HH, b2, cnt, nullptr, agg, HH, 0);

        // u1 = relu([x,agg] @ uw1 + ub1)   (2048,256,K=384, split at 128)
        gemm_k<<<dim3(HH/64, ROWS/64), 256>>>(ROWS, HH, DD + HH, DD,
            x, DD, agg, HH, uw1, HH, ub1, nullptr, nullptr, u1, HH, GRELU);

        // u = u1 @ uw2 + ub2   (2048,128,K=256)
        gemm_k<<<dim3(DD/64, ROWS/64), 256>>>(ROWS, DD, HH, 0,
            u1, HH, nullptr, 0, uw2, DD, ub2, nullptr, nullptr, u, DD, 0);

        // x = LN(x + u*mi)*mi
        ln_kernel<<<ROWS/8, 256>>>(u, mask, lg, lb, x);
    }

    // z = relu(x @ out_w1 + out_b1)  -> reuse u1
    gemm_k<<<dim3(HH/64, ROWS/64), 256>>>(ROWS, HH, DD, 0,
        x, DD, nullptr, 0, out_w1, HH, out_b1, nullptr, nullptr, u1, HH, GRELU);

    // out = (z @ out_w2 + out_b2) * mask
    gemm_k<<<dim3(DD/64, ROWS/64), 256>>>(ROWS, DD, HH, 0,
        u1, HH, nullptr, 0, out_w2, DD, out_b2, nullptr, mask, out, DD, GMASK);
}